// round 10
// baseline (speedup 1.0000x reference)
#include <cuda_runtime.h>
#include <cuda_fp16.h>

#define N_NODES  100000
#define N_EDGES  3200000
#define N_FEAT   128
#define EMB      64
#define HID      64
#define N_SUB    500000
#define N_GRAPHS 1024
#define BN_EPS   1e-5f

// ---------------- scratch ----------------------------------------------------
__device__ int     g_idx64;
__device__ int     g_deg[N_NODES];
__device__ float   g_dinv[N_NODES];
__device__ int     g_rowptr[N_NODES + 1];
__device__ int     g_cursor[N_NODES];
__device__ int     g_src32[N_EDGES];
__device__ int     g_dst32[N_EDGES];
__device__ int     g_csr[N_EDGES];
__device__ int     g_bsums[128];
__device__ __half2 g_xwsh[N_NODES * 32];   // dinv*(x@W) as half2 pairs (12.8 MB)
__device__ __half2 g_h2[N_NODES * 32];     // relu'd embeddings, half2 (12.8 MB)
__device__ int     g_bcnt[N_GRAPHS];
__device__ int     g_boff[N_GRAPHS + 1];
__device__ int     g_bcur[N_GRAPHS];
__device__ int     g_memb[N_SUB];
__device__ float   g_z[N_GRAPHS * HID];

// ---------------- packed f32x2 helpers (Blackwell) ---------------------------
__device__ __forceinline__ unsigned long long fma2(unsigned long long a,
                                                   unsigned long long b,
                                                   unsigned long long c) {
    unsigned long long d;
    asm("fma.rn.f32x2 %0, %1, %2, %3;" : "=l"(d) : "l"(a), "l"(b), "l"(c));
    return d;
}
__device__ __forceinline__ unsigned long long pack2(float v) {
    unsigned long long r;
    unsigned int u = __float_as_uint(v);
    asm("mov.b64 %0, {%1, %1};" : "=l"(r) : "r"(u));
    return r;
}
__device__ __forceinline__ void unpack2(unsigned long long a, float& lo, float& hi) {
    unsigned int l, h;
    asm("mov.b64 {%0, %1}, %2;" : "=r"(l), "=r"(h) : "l"(a));
    lo = __uint_as_float(l); hi = __uint_as_float(h);
}

// ---------------- index dtype handling ---------------------------------------
__device__ __forceinline__ int load_idx(const void* p, long long i) {
    return g_idx64 ? (int)((const long long*)p)[i] : ((const int*)p)[i];
}

// ---------------- init: detect + zero ----------------------------------------
__global__ void k_init(const unsigned int* __restrict__ raw) {
    int i = blockIdx.x * blockDim.x + threadIdx.x;
    if (i == 0) {
        int all0 = 1;
        #pragma unroll
        for (int j = 1; j < 64; j += 2) all0 &= (raw[j] == 0u);
        g_idx64 = all0;
    }
    int stride = gridDim.x * blockDim.x;
    for (int j = i; j < N_NODES; j += stride) { g_deg[j] = 0; g_cursor[j] = 0; }
    if (i < N_GRAPHS) { g_bcnt[i] = 0; g_bcur[i] = 0; }
}

// ---------------- convert indices + degree histogram -------------------------
__global__ void k_hist(const void* __restrict__ ei) {
    int e = blockIdx.x * blockDim.x + threadIdx.x;
    if (e < N_EDGES) {
        int src = load_idx(ei, e);
        int dst = load_idx(ei, (long long)N_EDGES + e);
        src = min(max(src, 0), N_NODES - 1);
        dst = min(max(dst, 0), N_NODES - 1);
        g_src32[e] = src;
        g_dst32[e] = dst;
        atomicAdd(&g_deg[dst], 1);
    }
}

// ---------------- exclusive scan of g_deg -> g_rowptr (+ dinv) ---------------
__global__ void k_scan1() {
    __shared__ int s[1024];
    int t = threadIdx.x;
    int g = blockIdx.x * 1024 + t;
    int v = (g < N_NODES) ? g_deg[g] : 0;
    if (g < N_NODES) g_dinv[g] = rsqrtf((float)(v + 1));   // +1 self loop
    s[t] = v; __syncthreads();
    #pragma unroll
    for (int off = 1; off < 1024; off <<= 1) {
        int tmp = (t >= off) ? s[t - off] : 0;
        __syncthreads();
        s[t] += tmp;
        __syncthreads();
    }
    if (g < N_NODES) g_rowptr[g] = s[t] - v;
    if (t == 1023) g_bsums[blockIdx.x] = s[1023];
}

// parallel 128-wide scan of the 98 block sums (exclusive, in place)
__global__ void k_scan2(int nblk) {
    __shared__ int s[128];
    int t = threadIdx.x;
    int v = (t < nblk) ? g_bsums[t] : 0;
    s[t] = v; __syncthreads();
    #pragma unroll
    for (int off = 1; off < 128; off <<= 1) {
        int tmp = (t >= off) ? s[t - off] : 0;
        __syncthreads();
        s[t] += tmp;
        __syncthreads();
    }
    if (t < nblk) g_bsums[t] = s[t] - v;
}

__global__ void k_scan3() {
    int t = threadIdx.x;
    int g = blockIdx.x * 1024 + t;
    if (g < N_NODES) g_rowptr[g] += g_bsums[blockIdx.x];
    if (g == 0) g_rowptr[N_NODES] = N_EDGES;
}

// ---------------- CSR fill (int32 inputs) ------------------------------------
__global__ void k_fill() {
    int e = blockIdx.x * blockDim.x + threadIdx.x;
    if (e < N_EDGES) {
        int src = g_src32[e];
        int dst = g_dst32[e];
        int p = atomicAdd(&g_cursor[dst], 1);
        g_csr[g_rowptr[dst] + p] = src;
    }
}

// ---------------- encoder GEMM: xws = dinv * (x @ W), fp32x2 math ------------
__global__ void __launch_bounds__(256) k_gemm(const float* __restrict__ x,
                                              const float* __restrict__ W) {
    __shared__ unsigned long long sW[N_FEAT * 32];   // 32 KB
    int t = threadIdx.x;
    const unsigned long long* Wll = (const unsigned long long*)W;
    for (int i = t; i < N_FEAT * 32; i += 256) sW[i] = Wll[i];
    __syncthreads();

    int w = t >> 5, lane = t & 31;
    int row0 = blockIdx.x * 32 + w * 4;      // 100000 = 3125*32, no tail
    const float4* x4 = (const float4*)x;

    unsigned long long a0 = 0ull, a1 = 0ull, a2 = 0ull, a3 = 0ull;
    #pragma unroll 4
    for (int kk = 0; kk < 32; kk++) {
        float4 xa = __ldg(&x4[(long long)(row0 + 0) * 32 + kk]);
        float4 xb = __ldg(&x4[(long long)(row0 + 1) * 32 + kk]);
        float4 xc = __ldg(&x4[(long long)(row0 + 2) * 32 + kk]);
        float4 xd = __ldg(&x4[(long long)(row0 + 3) * 32 + kk]);
        const float* fa = (const float*)&xa;
        const float* fb = (const float*)&xb;
        const float* fc = (const float*)&xc;
        const float* fd = (const float*)&xd;
        #pragma unroll
        for (int j = 0; j < 4; j++) {
            unsigned long long wv = sW[(kk * 4 + j) * 32 + lane];
            a0 = fma2(pack2(fa[j]), wv, a0);
            a1 = fma2(pack2(fb[j]), wv, a1);
            a2 = fma2(pack2(fc[j]), wv, a2);
            a3 = fma2(pack2(fd[j]), wv, a3);
        }
    }
    float lo, hi, di;
    di = g_dinv[row0 + 0]; unpack2(a0, lo, hi);
    g_xwsh[(row0 + 0) * 32 + lane] = __floats2half2_rn(lo * di, hi * di);
    di = g_dinv[row0 + 1]; unpack2(a1, lo, hi);
    g_xwsh[(row0 + 1) * 32 + lane] = __floats2half2_rn(lo * di, hi * di);
    di = g_dinv[row0 + 2]; unpack2(a2, lo, hi);
    g_xwsh[(row0 + 2) * 32 + lane] = __floats2half2_rn(lo * di, hi * di);
    di = g_dinv[row0 + 3]; unpack2(a3, lo, hi);
    g_xwsh[(row0 + 3) * 32 + lane] = __floats2half2_rn(lo * di, hi * di);
}

// ---------------- aggregate: one warp per node, fp16 gather ------------------
__global__ void __launch_bounds__(256) k_agg(const float* __restrict__ b_enc) {
    int w = threadIdx.x >> 5, lane = threadIdx.x & 31;
    int node = blockIdx.x * 8 + w;
    if (node >= N_NODES) return;

    float2 self = __half22float2(g_xwsh[node * 32 + lane]);
    float ax = self.x, ay = self.y;

    int e = g_rowptr[node], end = g_rowptr[node + 1];
    for (; e + 7 < end; e += 8) {
        int i0 = g_csr[e],     i1 = g_csr[e + 1], i2 = g_csr[e + 2], i3 = g_csr[e + 3];
        int i4 = g_csr[e + 4], i5 = g_csr[e + 5], i6 = g_csr[e + 6], i7 = g_csr[e + 7];
        float2 v0 = __half22float2(g_xwsh[i0 * 32 + lane]);
        float2 v1 = __half22float2(g_xwsh[i1 * 32 + lane]);
        float2 v2 = __half22float2(g_xwsh[i2 * 32 + lane]);
        float2 v3 = __half22float2(g_xwsh[i3 * 32 + lane]);
        float2 v4 = __half22float2(g_xwsh[i4 * 32 + lane]);
        float2 v5 = __half22float2(g_xwsh[i5 * 32 + lane]);
        float2 v6 = __half22float2(g_xwsh[i6 * 32 + lane]);
        float2 v7 = __half22float2(g_xwsh[i7 * 32 + lane]);
        ax += (v0.x + v1.x) + (v2.x + v3.x) + (v4.x + v5.x) + (v6.x + v7.x);
        ay += (v0.y + v1.y) + (v2.y + v3.y) + (v4.y + v5.y) + (v6.y + v7.y);
    }
    for (; e < end; e++) {
        float2 v = __half22float2(g_xwsh[g_csr[e] * 32 + lane]);
        ax += v.x; ay += v.y;
    }

    float di = g_dinv[node];
    float2 bb = ((const float2*)b_enc)[lane];
    float hx = fmaxf(fmaf(di, ax, bb.x), 0.f);
    float hy = fmaxf(fmaf(di, ay, bb.y), 0.f);
    g_h2[node * 32 + lane] = __floats2half2_rn(hx, hy);
}

// ---------------- batch histogram (smem-privatized) --------------------------
__global__ void k_bhist(const void* __restrict__ batch) {
    __shared__ int s[N_GRAPHS];
    int t = threadIdx.x;
    for (int i = t; i < N_GRAPHS; i += blockDim.x) s[i] = 0;
    __syncthreads();
    int stride = gridDim.x * blockDim.x;
    for (int j = blockIdx.x * blockDim.x + t; j < N_SUB; j += stride) {
        int b = load_idx(batch, j);
        b = min(max(b, 0), N_GRAPHS - 1);
        atomicAdd(&s[b], 1);
    }
    __syncthreads();
    for (int i = t; i < N_GRAPHS; i += blockDim.x)
        if (s[i]) atomicAdd(&g_bcnt[i], s[i]);
}

__global__ void k_bscan() {
    __shared__ int s[N_GRAPHS];
    int t = threadIdx.x;
    int v = g_bcnt[t];
    s[t] = v; __syncthreads();
    #pragma unroll
    for (int off = 1; off < N_GRAPHS; off <<= 1) {
        int tmp = (t >= off) ? s[t - off] : 0;
        __syncthreads();
        s[t] += tmp;
        __syncthreads();
    }
    g_boff[t] = s[t] - v;
    if (t == N_GRAPHS - 1) g_boff[N_GRAPHS] = s[t];
}

__global__ void k_bfill(const void* __restrict__ batch,
                        const void* __restrict__ subidx) {
    int j = blockIdx.x * blockDim.x + threadIdx.x;
    if (j < N_SUB) {
        int b = load_idx(batch, j);
        b = min(max(b, 0), N_GRAPHS - 1);
        int node = load_idx(subidx, j);
        node = min(max(node, 0), N_NODES - 1);
        int p = atomicAdd(&g_bcur[b], 1);
        g_memb[g_boff[b] + p] = node;
    }
}

// ---------------- fused pooling + MLP layer 1 --------------------------------
__global__ void __launch_bounds__(256) k_poolmlp(const float* __restrict__ W1,
                                                 const float* __restrict__ b1) {
    __shared__ float2 sred[256];
    __shared__ float p[EMB];
    int g = blockIdx.x, t = threadIdx.x;
    int pr = t & 31, slot = t >> 5;
    int beg = g_boff[g], end = g_boff[g + 1];

    float a0x = 0.f, a0y = 0.f, a1x = 0.f, a1y = 0.f;
    float a2x = 0.f, a2y = 0.f, a3x = 0.f, a3y = 0.f;
    int i = beg + slot;
    for (; i + 24 < end; i += 32) {
        int n0 = g_memb[i], n1 = g_memb[i + 8], n2 = g_memb[i + 16], n3 = g_memb[i + 24];
        float2 v0 = __half22float2(g_h2[n0 * 32 + pr]);
        float2 v1 = __half22float2(g_h2[n1 * 32 + pr]);
        float2 v2 = __half22float2(g_h2[n2 * 32 + pr]);
        float2 v3 = __half22float2(g_h2[n3 * 32 + pr]);
        a0x += v0.x; a0y += v0.y;
        a1x += v1.x; a1y += v1.y;
        a2x += v2.x; a2y += v2.y;
        a3x += v3.x; a3y += v3.y;
    }
    for (; i < end; i += 8) {
        float2 v = __half22float2(g_h2[g_memb[i] * 32 + pr]);
        a0x += v.x; a0y += v.y;
    }
    sred[t] = make_float2((a0x + a1x) + (a2x + a3x), (a0y + a1y) + (a2y + a3y));
    __syncthreads();
    if (slot < 4) { sred[t].x += sred[t + 128].x; sred[t].y += sred[t + 128].y; }
    __syncthreads();
    if (slot < 2) { sred[t].x += sred[t + 64].x;  sred[t].y += sred[t + 64].y; }
    __syncthreads();
    if (slot == 0) {
        float inv = 1.0f / fmaxf((float)(end - beg), 1.0f);
        p[2 * pr]     = (sred[pr].x + sred[pr + 32].x) * inv;
        p[2 * pr + 1] = (sred[pr].y + sred[pr + 32].y) * inv;
    }
    __syncthreads();
    if (t < HID) {
        float a = b1[t];
        #pragma unroll 8
        for (int k = 0; k < EMB; k++)
            a = fmaf(p[k], W1[k * HID + t], a);
        g_z[g * HID + t] = fmaxf(a, 0.f);
    }
}

// ---------------- BN (batch stats) + final linear, fused ---------------------
__global__ void __launch_bounds__(1024) k_bnfinal(const float* __restrict__ gamma,
                                                  const float* __restrict__ beta,
                                                  const float* __restrict__ W2,
                                                  const float* __restrict__ b2,
                                                  float* __restrict__ out) {
    __shared__ float a_s[HID], d_s[HID];
    int t = threadIdx.x, w = t >> 5, lane = t & 31;
    for (int ff = w; ff < HID; ff += 32) {
        float s = 0.f, s2 = 0.f;
        for (int r = lane; r < N_GRAPHS; r += 32) {
            float v = g_z[r * HID + ff];
            s += v; s2 = fmaf(v, v, s2);
        }
        #pragma unroll
        for (int o = 16; o; o >>= 1) {
            s  += __shfl_down_sync(0xffffffffu, s,  o);
            s2 += __shfl_down_sync(0xffffffffu, s2, o);
        }
        if (lane == 0) {
            float mu  = s  * (1.0f / N_GRAPHS);
            float var = s2 * (1.0f / N_GRAPHS) - mu * mu;
            float rs  = rsqrtf(var + BN_EPS);
            float a   = rs * gamma[ff] * W2[ff];
            a_s[ff] = a;
            d_s[ff] = beta[ff] * W2[ff] - mu * a;
        }
    }
    __syncthreads();
    float acc = b2[0];
    const float* zr = &g_z[t * HID];
    #pragma unroll
    for (int f = 0; f < HID; f++)
        acc += fmaf(zr[f], a_s[f], d_s[f]);
    out[t] = acc;
}

// ---------------- launch -----------------------------------------------------
extern "C" void kernel_launch(void* const* d_in, const int* in_sizes, int n_in,
                              void* d_out, int out_size) {
    const float* x      = (const float*)d_in[0];
    const void*  ei     = d_in[1];
    const void*  subidx = d_in[2];
    const void*  batch  = d_in[3];
    const float* W_enc  = (const float*)d_in[4];
    const float* b_enc  = (const float*)d_in[5];
    const float* W1     = (const float*)d_in[6];
    const float* b1     = (const float*)d_in[7];
    const float* gamma  = (const float*)d_in[8];
    const float* beta   = (const float*)d_in[9];
    const float* W2     = (const float*)d_in[10];
    const float* b2     = (const float*)d_in[11];
    float* out = (float*)d_out;

    const int EB = (N_EDGES + 255) / 256;     // 12500
    const int NB = (N_NODES + 1023) / 1024;   // 98

    // single stream; k_gemm hoisted to 4th submitted launch (needs only g_dinv
    // from k_scan1) so ncu's -s 5 -c 1 window samples it next round.
    k_init<<<512, 256>>>((const unsigned int*)ei);
    k_hist<<<EB, 256>>>(ei);
    k_scan1<<<NB, 1024>>>();
    k_gemm<<<N_NODES / 32, 256>>>(x, W_enc);
    k_scan2<<<1, 128>>>(NB);
    k_scan3<<<NB, 1024>>>();
    k_fill<<<EB, 256>>>();
    k_agg<<<(N_NODES + 7) / 8, 256>>>(b_enc);
    k_bhist<<<256, 256>>>(batch);
    k_bscan<<<1, N_GRAPHS>>>();
    k_bfill<<<(N_SUB + 255) / 256, 256>>>(batch, subidx);
    k_poolmlp<<<N_GRAPHS, 256>>>(W1, b1);
    k_bnfinal<<<1, 1024>>>(gamma, beta, W2, b2, out);
}

// round 11
// speedup vs baseline: 1.0325x; 1.0325x over previous
#include <cuda_runtime.h>
#include <cuda_fp16.h>

#define N_NODES  100000
#define N_EDGES  3200000
#define N_FEAT   128
#define EMB      64
#define HID      64
#define N_SUB    500000
#define N_GRAPHS 1024
#define BN_EPS   1e-5f

// ---------------- scratch ----------------------------------------------------
__device__ int     g_idx64;
__device__ int     g_deg[N_NODES];
__device__ float   g_dinv[N_NODES];
__device__ int     g_rowptr[N_NODES + 1];
__device__ int     g_cursor[N_NODES];
__device__ int     g_src32[N_EDGES];
__device__ int     g_dst32[N_EDGES];
__device__ int     g_csr[N_EDGES];
__device__ int     g_bsums[128];
__device__ __half2 g_xwsh[N_NODES * 32];   // dinv*(x@W) as half2 pairs (12.8 MB)
__device__ __half2 g_h2[N_NODES * 32];     // relu'd embeddings, half2 (12.8 MB)
__device__ int     g_bcnt[N_GRAPHS];
__device__ int     g_boff[N_GRAPHS + 1];
__device__ int     g_bcur[N_GRAPHS];
__device__ int     g_memb[N_SUB];
__device__ float   g_z[N_GRAPHS * HID];

// ---------------- packed f32x2 helpers (Blackwell) ---------------------------
__device__ __forceinline__ unsigned long long fma2(unsigned long long a,
                                                   unsigned long long b,
                                                   unsigned long long c) {
    unsigned long long d;
    asm("fma.rn.f32x2 %0, %1, %2, %3;" : "=l"(d) : "l"(a), "l"(b), "l"(c));
    return d;
}
__device__ __forceinline__ unsigned long long pack2(float v) {
    unsigned long long r;
    unsigned int u = __float_as_uint(v);
    asm("mov.b64 %0, {%1, %1};" : "=l"(r) : "r"(u));
    return r;
}
__device__ __forceinline__ void unpack2(unsigned long long a, float& lo, float& hi) {
    unsigned int l, h;
    asm("mov.b64 {%0, %1}, %2;" : "=r"(l), "=r"(h) : "l"(a));
    lo = __uint_as_float(l); hi = __uint_as_float(h);
}

// ---------------- index dtype handling ---------------------------------------
__device__ __forceinline__ int load_idx(const void* p, long long i) {
    return g_idx64 ? (int)((const long long*)p)[i] : ((const int*)p)[i];
}

// ---------------- init: detect + zero ----------------------------------------
__global__ void k_init(const unsigned int* __restrict__ raw) {
    int i = blockIdx.x * blockDim.x + threadIdx.x;
    if (i == 0) {
        int all0 = 1;
        #pragma unroll
        for (int j = 1; j < 64; j += 2) all0 &= (raw[j] == 0u);
        g_idx64 = all0;
    }
    int stride = gridDim.x * blockDim.x;
    for (int j = i; j < N_NODES; j += stride) { g_deg[j] = 0; g_cursor[j] = 0; }
    if (i < N_GRAPHS) { g_bcnt[i] = 0; g_bcur[i] = 0; }
}

// ---------------- convert indices + degree histogram -------------------------
__global__ void k_hist(const void* __restrict__ ei) {
    int e = blockIdx.x * blockDim.x + threadIdx.x;
    if (e < N_EDGES) {
        int src = load_idx(ei, e);
        int dst = load_idx(ei, (long long)N_EDGES + e);
        src = min(max(src, 0), N_NODES - 1);
        dst = min(max(dst, 0), N_NODES - 1);
        g_src32[e] = src;
        g_dst32[e] = dst;
        atomicAdd(&g_deg[dst], 1);
    }
}

// ---------------- exclusive scan of g_deg -> g_rowptr (+ dinv) ---------------
__global__ void k_scan1() {
    __shared__ int s[1024];
    int t = threadIdx.x;
    int g = blockIdx.x * 1024 + t;
    int v = (g < N_NODES) ? g_deg[g] : 0;
    if (g < N_NODES) g_dinv[g] = rsqrtf((float)(v + 1));   // +1 self loop
    s[t] = v; __syncthreads();
    #pragma unroll
    for (int off = 1; off < 1024; off <<= 1) {
        int tmp = (t >= off) ? s[t - off] : 0;
        __syncthreads();
        s[t] += tmp;
        __syncthreads();
    }
    if (g < N_NODES) g_rowptr[g] = s[t] - v;
    if (t == 1023) g_bsums[blockIdx.x] = s[1023];
}

// parallel 128-wide scan of the 98 block sums (exclusive, in place)
__global__ void k_scan2(int nblk) {
    __shared__ int s[128];
    int t = threadIdx.x;
    int v = (t < nblk) ? g_bsums[t] : 0;
    s[t] = v; __syncthreads();
    #pragma unroll
    for (int off = 1; off < 128; off <<= 1) {
        int tmp = (t >= off) ? s[t - off] : 0;
        __syncthreads();
        s[t] += tmp;
        __syncthreads();
    }
    if (t < nblk) g_bsums[t] = s[t] - v;
}

__global__ void k_scan3() {
    int t = threadIdx.x;
    int g = blockIdx.x * 1024 + t;
    if (g < N_NODES) g_rowptr[g] += g_bsums[blockIdx.x];
    if (g == 0) g_rowptr[N_NODES] = N_EDGES;
}

// ---------------- CSR fill (int32 inputs) ------------------------------------
__global__ void k_fill() {
    int e = blockIdx.x * blockDim.x + threadIdx.x;
    if (e < N_EDGES) {
        int src = g_src32[e];
        int dst = g_dst32[e];
        int p = atomicAdd(&g_cursor[dst], 1);
        g_csr[g_rowptr[dst] + p] = src;
    }
}

// ---------------- encoder GEMM: xws = dinv * (x @ W) -------------------------
// 8 rows per THREAD (one warp = 8 rows x 64 cols): each LDS.64 of a W pair
// feeds 8 FFMA2s, halving smem phase traffic vs the 4-row version.
__global__ void __launch_bounds__(256) k_gemm(const float* __restrict__ x,
                                              const float* __restrict__ W) {
    __shared__ unsigned long long sW[N_FEAT * 32];   // 32 KB
    int t = threadIdx.x;
    const unsigned long long* Wll = (const unsigned long long*)W;
    for (int i = t; i < N_FEAT * 32; i += 256) sW[i] = Wll[i];
    __syncthreads();

    int w = t >> 5, lane = t & 31;
    int row0 = blockIdx.x * 64 + w * 8;
    // 100000 = 1562*64 + 32; the remainder is exactly 4 full warps of 8 rows,
    // so every warp is entirely in range or entirely out.
    if (row0 >= N_NODES) return;

    const float4* x4 = (const float4*)x;
    unsigned long long acc[8];
    #pragma unroll
    for (int r = 0; r < 8; r++) acc[r] = 0ull;

    #pragma unroll 2
    for (int kk = 0; kk < 32; kk++) {
        float4 xr[8];
        #pragma unroll
        for (int r = 0; r < 8; r++)
            xr[r] = __ldg(&x4[(long long)(row0 + r) * 32 + kk]);
        #pragma unroll
        for (int j = 0; j < 4; j++) {
            unsigned long long wv = sW[(kk * 4 + j) * 32 + lane];
            #pragma unroll
            for (int r = 0; r < 8; r++)
                acc[r] = fma2(pack2(((const float*)&xr[r])[j]), wv, acc[r]);
        }
    }
    #pragma unroll
    for (int r = 0; r < 8; r++) {
        float lo, hi;
        float di = g_dinv[row0 + r];
        unpack2(acc[r], lo, hi);
        g_xwsh[(row0 + r) * 32 + lane] = __floats2half2_rn(lo * di, hi * di);
    }
}

// ---------------- aggregate: one warp per node, fp16 gather ------------------
__global__ void __launch_bounds__(256) k_agg(const float* __restrict__ b_enc) {
    int w = threadIdx.x >> 5, lane = threadIdx.x & 31;
    int node = blockIdx.x * 8 + w;
    if (node >= N_NODES) return;

    float2 self = __half22float2(g_xwsh[node * 32 + lane]);
    float ax = self.x, ay = self.y;

    int e = g_rowptr[node], end = g_rowptr[node + 1];
    for (; e + 7 < end; e += 8) {
        int i0 = g_csr[e],     i1 = g_csr[e + 1], i2 = g_csr[e + 2], i3 = g_csr[e + 3];
        int i4 = g_csr[e + 4], i5 = g_csr[e + 5], i6 = g_csr[e + 6], i7 = g_csr[e + 7];
        float2 v0 = __half22float2(g_xwsh[i0 * 32 + lane]);
        float2 v1 = __half22float2(g_xwsh[i1 * 32 + lane]);
        float2 v2 = __half22float2(g_xwsh[i2 * 32 + lane]);
        float2 v3 = __half22float2(g_xwsh[i3 * 32 + lane]);
        float2 v4 = __half22float2(g_xwsh[i4 * 32 + lane]);
        float2 v5 = __half22float2(g_xwsh[i5 * 32 + lane]);
        float2 v6 = __half22float2(g_xwsh[i6 * 32 + lane]);
        float2 v7 = __half22float2(g_xwsh[i7 * 32 + lane]);
        ax += (v0.x + v1.x) + (v2.x + v3.x) + (v4.x + v5.x) + (v6.x + v7.x);
        ay += (v0.y + v1.y) + (v2.y + v3.y) + (v4.y + v5.y) + (v6.y + v7.y);
    }
    for (; e < end; e++) {
        float2 v = __half22float2(g_xwsh[g_csr[e] * 32 + lane]);
        ax += v.x; ay += v.y;
    }

    float di = g_dinv[node];
    float2 bb = ((const float2*)b_enc)[lane];
    float hx = fmaxf(fmaf(di, ax, bb.x), 0.f);
    float hy = fmaxf(fmaf(di, ay, bb.y), 0.f);
    g_h2[node * 32 + lane] = __floats2half2_rn(hx, hy);
}

// ---------------- batch histogram (smem-privatized) --------------------------
__global__ void k_bhist(const void* __restrict__ batch) {
    __shared__ int s[N_GRAPHS];
    int t = threadIdx.x;
    for (int i = t; i < N_GRAPHS; i += blockDim.x) s[i] = 0;
    __syncthreads();
    int stride = gridDim.x * blockDim.x;
    for (int j = blockIdx.x * blockDim.x + t; j < N_SUB; j += stride) {
        int b = load_idx(batch, j);
        b = min(max(b, 0), N_GRAPHS - 1);
        atomicAdd(&s[b], 1);
    }
    __syncthreads();
    for (int i = t; i < N_GRAPHS; i += blockDim.x)
        if (s[i]) atomicAdd(&g_bcnt[i], s[i]);
}

__global__ void k_bscan() {
    __shared__ int s[N_GRAPHS];
    int t = threadIdx.x;
    int v = g_bcnt[t];
    s[t] = v; __syncthreads();
    #pragma unroll
    for (int off = 1; off < N_GRAPHS; off <<= 1) {
        int tmp = (t >= off) ? s[t - off] : 0;
        __syncthreads();
        s[t] += tmp;
        __syncthreads();
    }
    g_boff[t] = s[t] - v;
    if (t == N_GRAPHS - 1) g_boff[N_GRAPHS] = s[t];
}

__global__ void k_bfill(const void* __restrict__ batch,
                        const void* __restrict__ subidx) {
    int j = blockIdx.x * blockDim.x + threadIdx.x;
    if (j < N_SUB) {
        int b = load_idx(batch, j);
        b = min(max(b, 0), N_GRAPHS - 1);
        int node = load_idx(subidx, j);
        node = min(max(node, 0), N_NODES - 1);
        int p = atomicAdd(&g_bcur[b], 1);
        g_memb[g_boff[b] + p] = node;
    }
}

// ---------------- fused pooling + MLP layer 1 --------------------------------
__global__ void __launch_bounds__(256) k_poolmlp(const float* __restrict__ W1,
                                                 const float* __restrict__ b1) {
    __shared__ float2 sred[256];
    __shared__ float p[EMB];
    int g = blockIdx.x, t = threadIdx.x;
    int pr = t & 31, slot = t >> 5;
    int beg = g_boff[g], end = g_boff[g + 1];

    float a0x = 0.f, a0y = 0.f, a1x = 0.f, a1y = 0.f;
    float a2x = 0.f, a2y = 0.f, a3x = 0.f, a3y = 0.f;
    int i = beg + slot;
    for (; i + 24 < end; i += 32) {
        int n0 = g_memb[i], n1 = g_memb[i + 8], n2 = g_memb[i + 16], n3 = g_memb[i + 24];
        float2 v0 = __half22float2(g_h2[n0 * 32 + pr]);
        float2 v1 = __half22float2(g_h2[n1 * 32 + pr]);
        float2 v2 = __half22float2(g_h2[n2 * 32 + pr]);
        float2 v3 = __half22float2(g_h2[n3 * 32 + pr]);
        a0x += v0.x; a0y += v0.y;
        a1x += v1.x; a1y += v1.y;
        a2x += v2.x; a2y += v2.y;
        a3x += v3.x; a3y += v3.y;
    }
    for (; i < end; i += 8) {
        float2 v = __half22float2(g_h2[g_memb[i] * 32 + pr]);
        a0x += v.x; a0y += v.y;
    }
    sred[t] = make_float2((a0x + a1x) + (a2x + a3x), (a0y + a1y) + (a2y + a3y));
    __syncthreads();
    if (slot < 4) { sred[t].x += sred[t + 128].x; sred[t].y += sred[t + 128].y; }
    __syncthreads();
    if (slot < 2) { sred[t].x += sred[t + 64].x;  sred[t].y += sred[t + 64].y; }
    __syncthreads();
    if (slot == 0) {
        float inv = 1.0f / fmaxf((float)(end - beg), 1.0f);
        p[2 * pr]     = (sred[pr].x + sred[pr + 32].x) * inv;
        p[2 * pr + 1] = (sred[pr].y + sred[pr + 32].y) * inv;
    }
    __syncthreads();
    if (t < HID) {
        float a = b1[t];
        #pragma unroll 8
        for (int k = 0; k < EMB; k++)
            a = fmaf(p[k], W1[k * HID + t], a);
        g_z[g * HID + t] = fmaxf(a, 0.f);
    }
}

// ---------------- BN (batch stats) + final linear, fused ---------------------
__global__ void __launch_bounds__(1024) k_bnfinal(const float* __restrict__ gamma,
                                                  const float* __restrict__ beta,
                                                  const float* __restrict__ W2,
                                                  const float* __restrict__ b2,
                                                  float* __restrict__ out) {
    __shared__ float a_s[HID], d_s[HID];
    int t = threadIdx.x, w = t >> 5, lane = t & 31;
    for (int ff = w; ff < HID; ff += 32) {
        float s = 0.f, s2 = 0.f;
        for (int r = lane; r < N_GRAPHS; r += 32) {
            float v = g_z[r * HID + ff];
            s += v; s2 = fmaf(v, v, s2);
        }
        #pragma unroll
        for (int o = 16; o; o >>= 1) {
            s  += __shfl_down_sync(0xffffffffu, s,  o);
            s2 += __shfl_down_sync(0xffffffffu, s2, o);
        }
        if (lane == 0) {
            float mu  = s  * (1.0f / N_GRAPHS);
            float var = s2 * (1.0f / N_GRAPHS) - mu * mu;
            float rs  = rsqrtf(var + BN_EPS);
            float a   = rs * gamma[ff] * W2[ff];
            a_s[ff] = a;
            d_s[ff] = beta[ff] * W2[ff] - mu * a;
        }
    }
    __syncthreads();
    float acc = b2[0];
    const float* zr = &g_z[t * HID];
    #pragma unroll
    for (int f = 0; f < HID; f++)
        acc += fmaf(zr[f], a_s[f], d_s[f]);
    out[t] = acc;
}

// ---------------- launch -----------------------------------------------------
extern "C" void kernel_launch(void* const* d_in, const int* in_sizes, int n_in,
                              void* d_out, int out_size) {
    const float* x      = (const float*)d_in[0];
    const void*  ei     = d_in[1];
    const void*  subidx = d_in[2];
    const void*  batch  = d_in[3];
    const float* W_enc  = (const float*)d_in[4];
    const float* b_enc  = (const float*)d_in[5];
    const float* W1     = (const float*)d_in[6];
    const float* b1     = (const float*)d_in[7];
    const float* gamma  = (const float*)d_in[8];
    const float* beta   = (const float*)d_in[9];
    const float* W2     = (const float*)d_in[10];
    const float* b2     = (const float*)d_in[11];
    float* out = (float*)d_out;

    const int EB = (N_EDGES + 255) / 256;     // 12500
    const int NB = (N_NODES + 1023) / 1024;   // 98
    const int GB = (N_NODES + 63) / 64;       // 1563 (64 rows/block)

    k_init<<<512, 256>>>((const unsigned int*)ei);
    k_hist<<<EB, 256>>>(ei);
    k_scan1<<<NB, 1024>>>();
    k_gemm<<<GB, 256>>>(x, W_enc);
    k_scan2<<<1, 128>>>(NB);
    k_scan3<<<NB, 1024>>>();
    k_fill<<<EB, 256>>>();
    k_agg<<<(N_NODES + 7) / 8, 256>>>(b_enc);
    k_bhist<<<256, 256>>>(batch);
    k_bscan<<<1, N_GRAPHS>>>();
    k_bfill<<<(N_SUB + 255) / 256, 256>>>(batch, subidx);
    k_poolmlp<<<N_GRAPHS, 256>>>(W1, b1);
    k_bnfinal<<<1, 1024>>>(gamma, beta, W2, b2, out);
}

// round 14
// speedup vs baseline: 1.1468x; 1.1107x over previous
#include <cuda_runtime.h>
#include <cuda_fp16.h>

#define N_NODES  100000
#define N_EDGES  3200000
#define N_FEAT   128
#define EMB      64
#define HID      64
#define N_SUB    500000
#define N_GRAPHS 1024
#define BN_EPS   1e-5f

// ---------------- scratch ----------------------------------------------------
__device__ int     g_idx64;
__device__ int     g_deg[N_NODES];
__device__ float   g_dinv[N_NODES];
__device__ int     g_rowptr[N_NODES + 1];
__device__ int     g_cursor[N_NODES];
__device__ int     g_src32[N_EDGES];
__device__ int     g_dst32[N_EDGES];
__device__ int     g_csr[N_EDGES];
__device__ int     g_bsums[128];
__device__ __half2 g_xwsh[N_NODES * 32];   // dinv*(x@W) as half2 pairs (12.8 MB)
__device__ __half2 g_h2[N_NODES * 32];     // relu'd embeddings, half2 (12.8 MB)
__device__ int     g_bcnt[N_GRAPHS];
__device__ int     g_boff[N_GRAPHS + 1];
__device__ int     g_bcur[N_GRAPHS];
__device__ int     g_memb[N_SUB];
__device__ float   g_z[N_GRAPHS * HID];

// ---------------- packed f32x2 helpers (Blackwell) ---------------------------
__device__ __forceinline__ unsigned long long fma2(unsigned long long a,
                                                   unsigned long long b,
                                                   unsigned long long c) {
    unsigned long long d;
    asm("fma.rn.f32x2 %0, %1, %2, %3;" : "=l"(d) : "l"(a), "l"(b), "l"(c));
    return d;
}
__device__ __forceinline__ unsigned long long pack2(float v) {
    unsigned long long r;
    unsigned int u = __float_as_uint(v);
    asm("mov.b64 %0, {%1, %1};" : "=l"(r) : "r"(u));
    return r;
}
__device__ __forceinline__ void unpack2(unsigned long long a, float& lo, float& hi) {
    unsigned int l, h;
    asm("mov.b64 {%0, %1}, %2;" : "=r"(l), "=r"(h) : "l"(a));
    lo = __uint_as_float(l); hi = __uint_as_float(h);
}

// ---------------- index dtype handling ---------------------------------------
__device__ __forceinline__ int load_idx(const void* p, long long i) {
    return g_idx64 ? (int)((const long long*)p)[i] : ((const int*)p)[i];
}

// ---------------- init: detect + zero ----------------------------------------
__global__ void k_init(const unsigned int* __restrict__ raw) {
    int i = blockIdx.x * blockDim.x + threadIdx.x;
    if (i == 0) {
        int all0 = 1;
        #pragma unroll
        for (int j = 1; j < 64; j += 2) all0 &= (raw[j] == 0u);
        g_idx64 = all0;
    }
    int stride = gridDim.x * blockDim.x;
    for (int j = i; j < N_NODES; j += stride) { g_deg[j] = 0; g_cursor[j] = 0; }
    if (i < N_GRAPHS) { g_bcnt[i] = 0; g_bcur[i] = 0; }
}

// ---------------- convert indices + degree histogram -------------------------
__global__ void k_hist(const void* __restrict__ ei) {
    int e = blockIdx.x * blockDim.x + threadIdx.x;
    if (e < N_EDGES) {
        int src = load_idx(ei, e);
        int dst = load_idx(ei, (long long)N_EDGES + e);
        src = min(max(src, 0), N_NODES - 1);
        dst = min(max(dst, 0), N_NODES - 1);
        g_src32[e] = src;
        g_dst32[e] = dst;
        atomicAdd(&g_deg[dst], 1);
    }
}

// ---------------- exclusive scan of g_deg -> g_rowptr (+ dinv) ---------------
__global__ void k_scan1() {
    __shared__ int s[1024];
    int t = threadIdx.x;
    int g = blockIdx.x * 1024 + t;
    int v = (g < N_NODES) ? g_deg[g] : 0;
    if (g < N_NODES) g_dinv[g] = rsqrtf((float)(v + 1));   // +1 self loop
    s[t] = v; __syncthreads();
    #pragma unroll
    for (int off = 1; off < 1024; off <<= 1) {
        int tmp = (t >= off) ? s[t - off] : 0;
        __syncthreads();
        s[t] += tmp;
        __syncthreads();
    }
    if (g < N_NODES) g_rowptr[g] = s[t] - v;
    if (t == 1023) g_bsums[blockIdx.x] = s[1023];
}

// parallel 128-wide scan of the 98 block sums (exclusive, in place)
__global__ void k_scan2(int nblk) {
    __shared__ int s[128];
    int t = threadIdx.x;
    int v = (t < nblk) ? g_bsums[t] : 0;
    s[t] = v; __syncthreads();
    #pragma unroll
    for (int off = 1; off < 128; off <<= 1) {
        int tmp = (t >= off) ? s[t - off] : 0;
        __syncthreads();
        s[t] += tmp;
        __syncthreads();
    }
    if (t < nblk) g_bsums[t] = s[t] - v;
}

__global__ void k_scan3() {
    int t = threadIdx.x;
    int g = blockIdx.x * 1024 + t;
    if (g < N_NODES) g_rowptr[g] += g_bsums[blockIdx.x];
    if (g == 0) g_rowptr[N_NODES] = N_EDGES;
}

// ---------------- CSR fill (int32 inputs) ------------------------------------
__global__ void k_fill() {
    int e = blockIdx.x * blockDim.x + threadIdx.x;
    if (e < N_EDGES) {
        int src = g_src32[e];
        int dst = g_dst32[e];
        int p = atomicAdd(&g_cursor[dst], 1);
        g_csr[g_rowptr[dst] + p] = src;
    }
}

// ---------------- encoder GEMM: xws = dinv * (x @ W) -------------------------
// 64-row x tile staged in smem (coalesced LDG.128), mainloop reads x via
// conflict-free broadcast LDS.128 (29-cyc) instead of 577-cyc broadcast LDG.
// 8 rows per thread: each W LDS.64 feeds 8 FFMA2s. Dynamic smem: 64 KB.
__global__ void __launch_bounds__(256) k_gemm(const float* __restrict__ x,
                                              const float* __restrict__ W) {
    extern __shared__ unsigned long long dsm[];
    unsigned long long* sW = dsm;                    // 4096 entries = 32 KB
    float4* sx4 = (float4*)(dsm + N_FEAT * 32);      // 64 rows x 32 float4 = 32 KB

    int t = threadIdx.x;
    const unsigned long long* Wll = (const unsigned long long*)W;
    #pragma unroll
    for (int i = 0; i < 16; i++) sW[t + i * 256] = Wll[t + i * 256];

    // stage x tile: rows [blockIdx*64, blockIdx*64+64), coalesced
    int base_row = blockIdx.x * 64;
    const float4* xg = (const float4*)x + (long long)base_row * 32;
    #pragma unroll
    for (int i = 0; i < 8; i++) {
        int idx = t + i * 256;                       // 0..2047
        if (base_row + (idx >> 5) < N_NODES)
            sx4[idx] = __ldg(&xg[idx]);
    }
    __syncthreads();

    int w = t >> 5, lane = t & 31;
    int row0 = w * 8;                                // local row of this thread's 8 rows
    if (base_row + row0 >= N_NODES) return;          // whole-warp exit (tail = 4 warps)

    unsigned long long acc[8];
    #pragma unroll
    for (int r = 0; r < 8; r++) acc[r] = 0ull;

    #pragma unroll 2
    for (int kk = 0; kk < 32; kk++) {
        float4 xr[8];
        #pragma unroll
        for (int r = 0; r < 8; r++)
            xr[r] = sx4[(row0 + r) * 32 + kk];       // broadcast LDS.128
        #pragma unroll
        for (int j = 0; j < 4; j++) {
            unsigned long long wv = sW[(kk * 4 + j) * 32 + lane];
            #pragma unroll
            for (int r = 0; r < 8; r++)
                acc[r] = fma2(pack2(((const float*)&xr[r])[j]), wv, acc[r]);
        }
    }
    #pragma unroll
    for (int r = 0; r < 8; r++) {
        float lo, hi;
        int row = base_row + row0 + r;
        float di = g_dinv[row];
        unpack2(acc[r], lo, hi);
        g_xwsh[row * 32 + lane] = __floats2half2_rn(lo * di, hi * di);
    }
}

// ---------------- aggregate: one warp per node, fp16 gather ------------------
__global__ void __launch_bounds__(256) k_agg(const float* __restrict__ b_enc) {
    int w = threadIdx.x >> 5, lane = threadIdx.x & 31;
    int node = blockIdx.x * 8 + w;
    if (node >= N_NODES) return;

    float2 self = __half22float2(g_xwsh[node * 32 + lane]);
    float ax = self.x, ay = self.y;

    int e = g_rowptr[node], end = g_rowptr[node + 1];
    for (; e + 7 < end; e += 8) {
        int i0 = g_csr[e],     i1 = g_csr[e + 1], i2 = g_csr[e + 2], i3 = g_csr[e + 3];
        int i4 = g_csr[e + 4], i5 = g_csr[e + 5], i6 = g_csr[e + 6], i7 = g_csr[e + 7];
        float2 v0 = __half22float2(g_xwsh[i0 * 32 + lane]);
        float2 v1 = __half22float2(g_xwsh[i1 * 32 + lane]);
        float2 v2 = __half22float2(g_xwsh[i2 * 32 + lane]);
        float2 v3 = __half22float2(g_xwsh[i3 * 32 + lane]);
        float2 v4 = __half22float2(g_xwsh[i4 * 32 + lane]);
        float2 v5 = __half22float2(g_xwsh[i5 * 32 + lane]);
        float2 v6 = __half22float2(g_xwsh[i6 * 32 + lane]);
        float2 v7 = __half22float2(g_xwsh[i7 * 32 + lane]);
        ax += (v0.x + v1.x) + (v2.x + v3.x) + (v4.x + v5.x) + (v6.x + v7.x);
        ay += (v0.y + v1.y) + (v2.y + v3.y) + (v4.y + v5.y) + (v6.y + v7.y);
    }
    for (; e < end; e++) {
        float2 v = __half22float2(g_xwsh[g_csr[e] * 32 + lane]);
        ax += v.x; ay += v.y;
    }

    float di = g_dinv[node];
    float2 bb = ((const float2*)b_enc)[lane];
    float hx = fmaxf(fmaf(di, ax, bb.x), 0.f);
    float hy = fmaxf(fmaf(di, ay, bb.y), 0.f);
    g_h2[node * 32 + lane] = __floats2half2_rn(hx, hy);
}

// ---------------- batch histogram (smem-privatized) --------------------------
__global__ void k_bhist(const void* __restrict__ batch) {
    __shared__ int s[N_GRAPHS];
    int t = threadIdx.x;
    for (int i = t; i < N_GRAPHS; i += blockDim.x) s[i] = 0;
    __syncthreads();
    int stride = gridDim.x * blockDim.x;
    for (int j = blockIdx.x * blockDim.x + t; j < N_SUB; j += stride) {
        int b = load_idx(batch, j);
        b = min(max(b, 0), N_GRAPHS - 1);
        atomicAdd(&s[b], 1);
    }
    __syncthreads();
    for (int i = t; i < N_GRAPHS; i += blockDim.x)
        if (s[i]) atomicAdd(&g_bcnt[i], s[i]);
}

__global__ void k_bscan() {
    __shared__ int s[N_GRAPHS];
    int t = threadIdx.x;
    int v = g_bcnt[t];
    s[t] = v; __syncthreads();
    #pragma unroll
    for (int off = 1; off < N_GRAPHS; off <<= 1) {
        int tmp = (t >= off) ? s[t - off] : 0;
        __syncthreads();
        s[t] += tmp;
        __syncthreads();
    }
    g_boff[t] = s[t] - v;
    if (t == N_GRAPHS - 1) g_boff[N_GRAPHS] = s[t];
}

__global__ void k_bfill(const void* __restrict__ batch,
                        const void* __restrict__ subidx) {
    int j = blockIdx.x * blockDim.x + threadIdx.x;
    if (j < N_SUB) {
        int b = load_idx(batch, j);
        b = min(max(b, 0), N_GRAPHS - 1);
        int node = load_idx(subidx, j);
        node = min(max(node, 0), N_NODES - 1);
        int p = atomicAdd(&g_bcur[b], 1);
        g_memb[g_boff[b] + p] = node;
    }
}

// ---------------- fused pooling + MLP layer 1 --------------------------------
__global__ void __launch_bounds__(256) k_poolmlp(const float* __restrict__ W1,
                                                 const float* __restrict__ b1) {
    __shared__ float2 sred[256];
    __shared__ float p[EMB];
    int g = blockIdx.x, t = threadIdx.x;
    int pr = t & 31, slot = t >> 5;
    int beg = g_boff[g], end = g_boff[g + 1];

    float a0x = 0.f, a0y = 0.f, a1x = 0.f, a1y = 0.f;
    float a2x = 0.f, a2y = 0.f, a3x = 0.f, a3y = 0.f;
    int i = beg + slot;
    for (; i + 24 < end; i += 32) {
        int n0 = g_memb[i], n1 = g_memb[i + 8], n2 = g_memb[i + 16], n3 = g_memb[i + 24];
        float2 v0 = __half22float2(g_h2[n0 * 32 + pr]);
        float2 v1 = __half22float2(g_h2[n1 * 32 + pr]);
        float2 v2 = __half22float2(g_h2[n2 * 32 + pr]);
        float2 v3 = __half22float2(g_h2[n3 * 32 + pr]);
        a0x += v0.x; a0y += v0.y;
        a1x += v1.x; a1y += v1.y;
        a2x += v2.x; a2y += v2.y;
        a3x += v3.x; a3y += v3.y;
    }
    for (; i < end; i += 8) {
        float2 v = __half22float2(g_h2[g_memb[i] * 32 + pr]);
        a0x += v.x; a0y += v.y;
    }
    sred[t] = make_float2((a0x + a1x) + (a2x + a3x), (a0y + a1y) + (a2y + a3y));
    __syncthreads();
    if (slot < 4) { sred[t].x += sred[t + 128].x; sred[t].y += sred[t + 128].y; }
    __syncthreads();
    if (slot < 2) { sred[t].x += sred[t + 64].x;  sred[t].y += sred[t + 64].y; }
    __syncthreads();
    if (slot == 0) {
        float inv = 1.0f / fmaxf((float)(end - beg), 1.0f);
        p[2 * pr]     = (sred[pr].x + sred[pr + 32].x) * inv;
        p[2 * pr + 1] = (sred[pr].y + sred[pr + 32].y) * inv;
    }
    __syncthreads();
    if (t < HID) {
        float a = b1[t];
        #pragma unroll 8
        for (int k = 0; k < EMB; k++)
            a = fmaf(p[k], W1[k * HID + t], a);
        g_z[g * HID + t] = fmaxf(a, 0.f);
    }
}

// ---------------- BN (batch stats) + final linear, fused ---------------------
__global__ void __launch_bounds__(1024) k_bnfinal(const float* __restrict__ gamma,
                                                  const float* __restrict__ beta,
                                                  const float* __restrict__ W2,
                                                  const float* __restrict__ b2,
                                                  float* __restrict__ out) {
    __shared__ float a_s[HID], d_s[HID];
    int t = threadIdx.x, w = t >> 5, lane = t & 31;
    for (int ff = w; ff < HID; ff += 32) {
        float s = 0.f, s2 = 0.f;
        for (int r = lane; r < N_GRAPHS; r += 32) {
            float v = g_z[r * HID + ff];
            s += v; s2 = fmaf(v, v, s2);
        }
        #pragma unroll
        for (int o = 16; o; o >>= 1) {
            s  += __shfl_down_sync(0xffffffffu, s,  o);
            s2 += __shfl_down_sync(0xffffffffu, s2, o);
        }
        if (lane == 0) {
            float mu  = s  * (1.0f / N_GRAPHS);
            float var = s2 * (1.0f / N_GRAPHS) - mu * mu;
            float rs  = rsqrtf(var + BN_EPS);
            float a   = rs * gamma[ff] * W2[ff];
            a_s[ff] = a;
            d_s[ff] = beta[ff] * W2[ff] - mu * a;
        }
    }
    __syncthreads();
    float acc = b2[0];
    const float* zr = &g_z[t * HID];
    #pragma unroll
    for (int f = 0; f < HID; f++)
        acc += fmaf(zr[f], a_s[f], d_s[f]);
    out[t] = acc;
}

// ---------------- launch -----------------------------------------------------
extern "C" void kernel_launch(void* const* d_in, const int* in_sizes, int n_in,
                              void* d_out, int out_size) {
    const float* x      = (const float*)d_in[0];
    const void*  ei     = d_in[1];
    const void*  subidx = d_in[2];
    const void*  batch  = d_in[3];
    const float* W_enc  = (const float*)d_in[4];
    const float* b_enc  = (const float*)d_in[5];
    const float* W1     = (const float*)d_in[6];
    const float* b1     = (const float*)d_in[7];
    const float* gamma  = (const float*)d_in[8];
    const float* beta   = (const float*)d_in[9];
    const float* W2     = (const float*)d_in[10];
    const float* b2     = (const float*)d_in[11];
    float* out = (float*)d_out;

    const int EB = (N_EDGES + 255) / 256;     // 12500
    const int NB = (N_NODES + 1023) / 1024;   // 98
    const int GB = (N_NODES + 63) / 64;       // 1563 (64 rows/block)
    const int GEMM_SMEM = 65536;              // 32KB W + 32KB x tile

    cudaFuncSetAttribute(k_gemm, cudaFuncAttributeMaxDynamicSharedMemorySize,
                         GEMM_SMEM);

    k_init<<<512, 256>>>((const unsigned int*)ei);
    k_hist<<<EB, 256>>>(ei);
    k_scan1<<<NB, 1024>>>();
    k_gemm<<<GB, 256, GEMM_SMEM>>>(x, W_enc);   // 4th launch -> profiled
    k_scan2<<<1, 128>>>(NB);
    k_scan3<<<NB, 1024>>>();
    k_fill<<<EB, 256>>>();
    k_agg<<<(N_NODES + 7) / 8, 256>>>(b_enc);
    k_bhist<<<256, 256>>>(batch);
    k_bscan<<<1, N_GRAPHS>>>();
    k_bfill<<<(N_SUB + 255) / 256, 256>>>(batch, subidx);
    k_poolmlp<<<N_GRAPHS, 256>>>(W1, b1);
    k_bnfinal<<<1, 1024>>>(gamma, beta, W2, b2, out);
}

// round 15
// speedup vs baseline: 1.1683x; 1.0188x over previous
#include <cuda_runtime.h>
#include <cuda_fp16.h>

#define N_NODES  100000
#define N_EDGES  3200000
#define N_FEAT   128
#define EMB      64
#define HID      64
#define N_SUB    500000
#define N_GRAPHS 1024
#define BN_EPS   1e-5f

// ---------------- scratch ----------------------------------------------------
__device__ int     g_idx64;
__device__ int     g_deg[N_NODES];
__device__ float   g_dinv[N_NODES];
__device__ int     g_rowptr[N_NODES + 1];
__device__ int     g_cursor[N_NODES];
__device__ int     g_src32[N_EDGES];
__device__ int     g_dst32[N_EDGES];
__device__ int     g_csr[N_EDGES];
__device__ int     g_bsums[128];
__device__ __half2 g_xwsh[N_NODES * 32];   // dinv*(x@W) as half2 pairs (12.8 MB)
__device__ __half2 g_h2[N_NODES * 32];     // relu'd embeddings, half2 (12.8 MB)
__device__ int     g_bcnt[N_GRAPHS];
__device__ int     g_boff[N_GRAPHS + 1];
__device__ int     g_bcur[N_GRAPHS];
__device__ int     g_memb[N_SUB];
__device__ float   g_z[N_GRAPHS * HID];

// ---------------- packed f32x2 helpers (Blackwell) ---------------------------
__device__ __forceinline__ unsigned long long fma2(unsigned long long a,
                                                   unsigned long long b,
                                                   unsigned long long c) {
    unsigned long long d;
    asm("fma.rn.f32x2 %0, %1, %2, %3;" : "=l"(d) : "l"(a), "l"(b), "l"(c));
    return d;
}
__device__ __forceinline__ unsigned long long pack2(float v) {
    unsigned long long r;
    unsigned int u = __float_as_uint(v);
    asm("mov.b64 %0, {%1, %1};" : "=l"(r) : "r"(u));
    return r;
}
__device__ __forceinline__ void unpack2(unsigned long long a, float& lo, float& hi) {
    unsigned int l, h;
    asm("mov.b64 {%0, %1}, %2;" : "=r"(l), "=r"(h) : "l"(a));
    lo = __uint_as_float(l); hi = __uint_as_float(h);
}

// ---------------- index dtype handling ---------------------------------------
__device__ __forceinline__ int load_idx(const void* p, long long i) {
    return g_idx64 ? (int)((const long long*)p)[i] : ((const int*)p)[i];
}

// ---------------- init: detect + zero ----------------------------------------
__global__ void k_init(const unsigned int* __restrict__ raw) {
    int i = blockIdx.x * blockDim.x + threadIdx.x;
    if (i == 0) {
        int all0 = 1;
        #pragma unroll
        for (int j = 1; j < 64; j += 2) all0 &= (raw[j] == 0u);
        g_idx64 = all0;
    }
    int stride = gridDim.x * blockDim.x;
    for (int j = i; j < N_NODES; j += stride) { g_deg[j] = 0; g_cursor[j] = 0; }
    if (i < N_GRAPHS) { g_bcnt[i] = 0; g_bcur[i] = 0; }
}

// ---------------- convert indices + degree histogram -------------------------
__global__ void k_hist(const void* __restrict__ ei) {
    int e = blockIdx.x * blockDim.x + threadIdx.x;
    if (e < N_EDGES) {
        int src = load_idx(ei, e);
        int dst = load_idx(ei, (long long)N_EDGES + e);
        src = min(max(src, 0), N_NODES - 1);
        dst = min(max(dst, 0), N_NODES - 1);
        g_src32[e] = src;
        g_dst32[e] = dst;
        atomicAdd(&g_deg[dst], 1);
    }
}

// ---------------- exclusive scan of g_deg -> g_rowptr (+ dinv) ---------------
__global__ void k_scan1() {
    __shared__ int s[1024];
    int t = threadIdx.x;
    int g = blockIdx.x * 1024 + t;
    int v = (g < N_NODES) ? g_deg[g] : 0;
    if (g < N_NODES) g_dinv[g] = rsqrtf((float)(v + 1));   // +1 self loop
    s[t] = v; __syncthreads();
    #pragma unroll
    for (int off = 1; off < 1024; off <<= 1) {
        int tmp = (t >= off) ? s[t - off] : 0;
        __syncthreads();
        s[t] += tmp;
        __syncthreads();
    }
    if (g < N_NODES) g_rowptr[g] = s[t] - v;
    if (t == 1023) g_bsums[blockIdx.x] = s[1023];
}

// merged scan2+scan3: every block redundantly scans the 98 block sums in smem
// (inclusive), then adds the exclusive prefix for its own block.
__global__ void k_scan3(int nblk) {
    __shared__ int s[128];
    int t = threadIdx.x;
    if (t < 128) s[t] = (t < nblk) ? g_bsums[t] : 0;
    __syncthreads();
    #pragma unroll
    for (int off = 1; off < 128; off <<= 1) {
        int tmp = (t >= off && t < 128) ? s[t - off] : 0;
        __syncthreads();
        if (t < 128) s[t] += tmp;
        __syncthreads();
    }
    int add = (blockIdx.x == 0) ? 0 : s[blockIdx.x - 1];
    int g = blockIdx.x * 1024 + t;
    if (g < N_NODES) g_rowptr[g] += add;
    if (g == 0) g_rowptr[N_NODES] = N_EDGES;
}

// ---------------- CSR fill (int32 inputs) ------------------------------------
__global__ void k_fill() {
    int e = blockIdx.x * blockDim.x + threadIdx.x;
    if (e < N_EDGES) {
        int src = g_src32[e];
        int dst = g_dst32[e];
        int p = atomicAdd(&g_cursor[dst], 1);
        g_csr[g_rowptr[dst] + p] = src;
    }
}

// ---------------- encoder GEMM: xws = dinv * (x @ W) -------------------------
// 64-row x tile staged in smem (coalesced LDG.128), mainloop reads x via
// conflict-free broadcast LDS.128; 8 rows/thread so each W LDS.64 feeds 8 FFMA2s.
__global__ void __launch_bounds__(256) k_gemm(const float* __restrict__ x,
                                              const float* __restrict__ W) {
    extern __shared__ unsigned long long dsm[];
    unsigned long long* sW = dsm;                    // 4096 entries = 32 KB
    float4* sx4 = (float4*)(dsm + N_FEAT * 32);      // 64 rows x 32 float4 = 32 KB

    int t = threadIdx.x;
    const unsigned long long* Wll = (const unsigned long long*)W;
    #pragma unroll
    for (int i = 0; i < 16; i++) sW[t + i * 256] = Wll[t + i * 256];

    int base_row = blockIdx.x * 64;
    const float4* xg = (const float4*)x + (long long)base_row * 32;
    #pragma unroll
    for (int i = 0; i < 8; i++) {
        int idx = t + i * 256;                       // 0..2047
        if (base_row + (idx >> 5) < N_NODES)
            sx4[idx] = __ldg(&xg[idx]);
    }
    __syncthreads();

    int w = t >> 5, lane = t & 31;
    int row0 = w * 8;
    if (base_row + row0 >= N_NODES) return;          // whole-warp exit

    unsigned long long acc[8];
    #pragma unroll
    for (int r = 0; r < 8; r++) acc[r] = 0ull;

    #pragma unroll 2
    for (int kk = 0; kk < 32; kk++) {
        float4 xr[8];
        #pragma unroll
        for (int r = 0; r < 8; r++)
            xr[r] = sx4[(row0 + r) * 32 + kk];       // broadcast LDS.128
        #pragma unroll
        for (int j = 0; j < 4; j++) {
            unsigned long long wv = sW[(kk * 4 + j) * 32 + lane];
            #pragma unroll
            for (int r = 0; r < 8; r++)
                acc[r] = fma2(pack2(((const float*)&xr[r])[j]), wv, acc[r]);
        }
    }
    #pragma unroll
    for (int r = 0; r < 8; r++) {
        float lo, hi;
        int row = base_row + row0 + r;
        float di = g_dinv[row];
        unpack2(acc[r], lo, hi);
        g_xwsh[row * 32 + lane] = __floats2half2_rn(lo * di, hi * di);
    }
}

// ---------------- aggregate: one warp per node, fp16 gather ------------------
__global__ void __launch_bounds__(256) k_agg(const float* __restrict__ b_enc) {
    int w = threadIdx.x >> 5, lane = threadIdx.x & 31;
    int node = blockIdx.x * 8 + w;
    if (node >= N_NODES) return;

    float2 self = __half22float2(g_xwsh[node * 32 + lane]);
    float ax = self.x, ay = self.y;

    int e = g_rowptr[node], end = g_rowptr[node + 1];
    for (; e + 7 < end; e += 8) {
        int i0 = g_csr[e],     i1 = g_csr[e + 1], i2 = g_csr[e + 2], i3 = g_csr[e + 3];
        int i4 = g_csr[e + 4], i5 = g_csr[e + 5], i6 = g_csr[e + 6], i7 = g_csr[e + 7];
        float2 v0 = __half22float2(g_xwsh[i0 * 32 + lane]);
        float2 v1 = __half22float2(g_xwsh[i1 * 32 + lane]);
        float2 v2 = __half22float2(g_xwsh[i2 * 32 + lane]);
        float2 v3 = __half22float2(g_xwsh[i3 * 32 + lane]);
        float2 v4 = __half22float2(g_xwsh[i4 * 32 + lane]);
        float2 v5 = __half22float2(g_xwsh[i5 * 32 + lane]);
        float2 v6 = __half22float2(g_xwsh[i6 * 32 + lane]);
        float2 v7 = __half22float2(g_xwsh[i7 * 32 + lane]);
        ax += (v0.x + v1.x) + (v2.x + v3.x) + (v4.x + v5.x) + (v6.x + v7.x);
        ay += (v0.y + v1.y) + (v2.y + v3.y) + (v4.y + v5.y) + (v6.y + v7.y);
    }
    for (; e < end; e++) {
        float2 v = __half22float2(g_xwsh[g_csr[e] * 32 + lane]);
        ax += v.x; ay += v.y;
    }

    float di = g_dinv[node];
    float2 bb = ((const float2*)b_enc)[lane];
    float hx = fmaxf(fmaf(di, ax, bb.x), 0.f);
    float hy = fmaxf(fmaf(di, ay, bb.y), 0.f);
    g_h2[node * 32 + lane] = __floats2half2_rn(hx, hy);
}

// ---------------- batch histogram (smem-privatized) --------------------------
__global__ void k_bhist(const void* __restrict__ batch) {
    __shared__ int s[N_GRAPHS];
    int t = threadIdx.x;
    for (int i = t; i < N_GRAPHS; i += blockDim.x) s[i] = 0;
    __syncthreads();
    int stride = gridDim.x * blockDim.x;
    for (int j = blockIdx.x * blockDim.x + t; j < N_SUB; j += stride) {
        int b = load_idx(batch, j);
        b = min(max(b, 0), N_GRAPHS - 1);
        atomicAdd(&s[b], 1);
    }
    __syncthreads();
    for (int i = t; i < N_GRAPHS; i += blockDim.x)
        if (s[i]) atomicAdd(&g_bcnt[i], s[i]);
}

__global__ void k_bscan() {
    __shared__ int s[N_GRAPHS];
    int t = threadIdx.x;
    int v = g_bcnt[t];
    s[t] = v; __syncthreads();
    #pragma unroll
    for (int off = 1; off < N_GRAPHS; off <<= 1) {
        int tmp = (t >= off) ? s[t - off] : 0;
        __syncthreads();
        s[t] += tmp;
        __syncthreads();
    }
    g_boff[t] = s[t] - v;
    if (t == N_GRAPHS - 1) g_boff[N_GRAPHS] = s[t];
}

__global__ void k_bfill(const void* __restrict__ batch,
                        const void* __restrict__ subidx) {
    int j = blockIdx.x * blockDim.x + threadIdx.x;
    if (j < N_SUB) {
        int b = load_idx(batch, j);
        b = min(max(b, 0), N_GRAPHS - 1);
        int node = load_idx(subidx, j);
        node = min(max(node, 0), N_NODES - 1);
        int p = atomicAdd(&g_bcur[b], 1);
        g_memb[g_boff[b] + p] = node;
    }
}

// ---------------- fused pooling + MLP layer 1 --------------------------------
__global__ void __launch_bounds__(256) k_poolmlp(const float* __restrict__ W1,
                                                 const float* __restrict__ b1) {
    __shared__ float2 sred[256];
    __shared__ float p[EMB];
    int g = blockIdx.x, t = threadIdx.x;
    int pr = t & 31, slot = t >> 5;
    int beg = g_boff[g], end = g_boff[g + 1];

    float a0x = 0.f, a0y = 0.f, a1x = 0.f, a1y = 0.f;
    float a2x = 0.f, a2y = 0.f, a3x = 0.f, a3y = 0.f;
    int i = beg + slot;
    for (; i + 24 < end; i += 32) {
        int n0 = g_memb[i], n1 = g_memb[i + 8], n2 = g_memb[i + 16], n3 = g_memb[i + 24];
        float2 v0 = __half22float2(g_h2[n0 * 32 + pr]);
        float2 v1 = __half22float2(g_h2[n1 * 32 + pr]);
        float2 v2 = __half22float2(g_h2[n2 * 32 + pr]);
        float2 v3 = __half22float2(g_h2[n3 * 32 + pr]);
        a0x += v0.x; a0y += v0.y;
        a1x += v1.x; a1y += v1.y;
        a2x += v2.x; a2y += v2.y;
        a3x += v3.x; a3y += v3.y;
    }
    for (; i < end; i += 8) {
        float2 v = __half22float2(g_h2[g_memb[i] * 32 + pr]);
        a0x += v.x; a0y += v.y;
    }
    sred[t] = make_float2((a0x + a1x) + (a2x + a3x), (a0y + a1y) + (a2y + a3y));
    __syncthreads();
    if (slot < 4) { sred[t].x += sred[t + 128].x; sred[t].y += sred[t + 128].y; }
    __syncthreads();
    if (slot < 2) { sred[t].x += sred[t + 64].x;  sred[t].y += sred[t + 64].y; }
    __syncthreads();
    if (slot == 0) {
        float inv = 1.0f / fmaxf((float)(end - beg), 1.0f);
        p[2 * pr]     = (sred[pr].x + sred[pr + 32].x) * inv;
        p[2 * pr + 1] = (sred[pr].y + sred[pr + 32].y) * inv;
    }
    __syncthreads();
    if (t < HID) {
        float a = b1[t];
        #pragma unroll 8
        for (int k = 0; k < EMB; k++)
            a = fmaf(p[k], W1[k * HID + t], a);
        g_z[g * HID + t] = fmaxf(a, 0.f);
    }
}

// ---------------- BN (batch stats) + final linear, fused ---------------------
__global__ void __launch_bounds__(1024) k_bnfinal(const float* __restrict__ gamma,
                                                  const float* __restrict__ beta,
                                                  const float* __restrict__ W2,
                                                  const float* __restrict__ b2,
                                                  float* __restrict__ out) {
    __shared__ float a_s[HID], d_s[HID];
    int t = threadIdx.x, w = t >> 5, lane = t & 31;
    for (int ff = w; ff < HID; ff += 32) {
        float s = 0.f, s2 = 0.f;
        for (int r = lane; r < N_GRAPHS; r += 32) {
            float v = g_z[r * HID + ff];
            s += v; s2 = fmaf(v, v, s2);
        }
        #pragma unroll
        for (int o = 16; o; o >>= 1) {
            s  += __shfl_down_sync(0xffffffffu, s,  o);
            s2 += __shfl_down_sync(0xffffffffu, s2, o);
        }
        if (lane == 0) {
            float mu  = s  * (1.0f / N_GRAPHS);
            float var = s2 * (1.0f / N_GRAPHS) - mu * mu;
            float rs  = rsqrtf(var + BN_EPS);
            float a   = rs * gamma[ff] * W2[ff];
            a_s[ff] = a;
            d_s[ff] = beta[ff] * W2[ff] - mu * a;
        }
    }
    __syncthreads();
    float acc = b2[0];
    const float* zr = &g_z[t * HID];
    #pragma unroll
    for (int f = 0; f < HID; f++)
        acc += fmaf(zr[f], a_s[f], d_s[f]);
    out[t] = acc;
}

// ---------------- side stream (lazy, created outside capture only) -----------
static cudaStream_t g_s2 = nullptr;
static cudaEvent_t  g_evScan1 = nullptr, g_evS2done = nullptr;

// ---------------- launch -----------------------------------------------------
extern "C" void kernel_launch(void* const* d_in, const int* in_sizes, int n_in,
                              void* d_out, int out_size) {
    const float* x      = (const float*)d_in[0];
    const void*  ei     = d_in[1];
    const void*  subidx = d_in[2];
    const void*  batch  = d_in[3];
    const float* W_enc  = (const float*)d_in[4];
    const float* b_enc  = (const float*)d_in[5];
    const float* W1     = (const float*)d_in[6];
    const float* b1     = (const float*)d_in[7];
    const float* gamma  = (const float*)d_in[8];
    const float* beta   = (const float*)d_in[9];
    const float* W2     = (const float*)d_in[10];
    const float* b2     = (const float*)d_in[11];
    float* out = (float*)d_out;

    const int EB = (N_EDGES + 255) / 256;     // 12500
    const int NB = (N_NODES + 1023) / 1024;   // 98
    const int GB = (N_NODES + 63) / 64;       // 1563 (64 rows/block)
    const int GEMM_SMEM = 65536;              // 32KB W + 32KB x tile

    // Lazy side-stream setup: only when NOT capturing (i.e. on the plain
    // correctness call). The captured graph then reuses the existing
    // stream/events via the standard event fork/join pattern.
    cudaStreamCaptureStatus cap = cudaStreamCaptureStatusNone;
    cudaStreamIsCapturing((cudaStream_t)0, &cap);
    if (cap == cudaStreamCaptureStatusNone && g_s2 == nullptr) {
        if (cudaStreamCreateWithFlags(&g_s2, cudaStreamNonBlocking) != cudaSuccess)
            g_s2 = nullptr;
        if (g_s2) {
            cudaEventCreateWithFlags(&g_evScan1, cudaEventDisableTiming);
            cudaEventCreateWithFlags(&g_evS2done, cudaEventDisableTiming);
        }
    }
    bool fork = (g_s2 && g_evScan1 && g_evS2done);

    cudaFuncSetAttribute(k_gemm, cudaFuncAttributeMaxDynamicSharedMemorySize,
                         GEMM_SMEM);

    k_init<<<512, 256>>>((const unsigned int*)ei);
    k_hist<<<EB, 256>>>(ei);
    k_scan1<<<NB, 1024>>>();

    if (fork) {
        // side stream: gemm (needs only g_dinv) then the batch chain
        cudaEventRecord(g_evScan1, 0);
        cudaStreamWaitEvent(g_s2, g_evScan1, 0);
        k_gemm<<<GB, 256, GEMM_SMEM, g_s2>>>(x, W_enc);   // 4th launch -> profiled
        k_bhist<<<256, 256, 0, g_s2>>>(batch);
        k_bscan<<<1, N_GRAPHS, 0, g_s2>>>();
        k_bfill<<<(N_SUB + 255) / 256, 256, 0, g_s2>>>(batch, subidx);
        cudaEventRecord(g_evS2done, g_s2);
    } else {
        k_gemm<<<GB, 256, GEMM_SMEM>>>(x, W_enc);
        k_bhist<<<256, 256>>>(batch);
        k_bscan<<<1, N_GRAPHS>>>();
        k_bfill<<<(N_SUB + 255) / 256, 256>>>(batch, subidx);
    }

    // main stream: finish CSR while gemm/batch run on the side stream
    k_scan3<<<NB, 1024>>>(NB);
    k_fill<<<EB, 256>>>();
    if (fork) cudaStreamWaitEvent(0, g_evS2done, 0);      // join before agg/pool
    k_agg<<<(N_NODES + 7) / 8, 256>>>(b_enc);
    k_poolmlp<<<N_GRAPHS, 256>>>(W1, b1);
    k_bnfinal<<<1, 1024>>>(gamma, beta, W2, b2, out);
}